// round 4
// baseline (speedup 1.0000x reference)
#include <cuda_runtime.h>
#include <cuda_bf16.h>

// CRF forward (log-semiring chain) in scaled-probability domain.
//
// Shapes (fixed for this problem instance):
//   feats      : (512, 1024, 32) f32
//   mask       : (512, 1024)     f32  (all ones, handled generically as 0/1 select)
//   transition : (32, 32)        f32
//   out        : (1024,)         f32
//
// Math: alpha_t[j] = feat[t,b,j] + logsumexp_i(alpha_{t-1}[i] + T[j,i])
// Rewritten with p = exp(alpha - M):  q = E p  (E = exp(T)),  p' = q * exp(feat),
// renormalize by max(p) every 8 steps, M += log(s).  Final:
// out[b] = M + log( sum_j p[j] * exp(T[END,j]) ).
//
// Mapping: warp = 2 batches (lanes 0-15 / 16-31), lane handles tags 2s, 2s+1.
// Broadcast p via width-16 shuffles; E rows live in registers (64 per lane).

#define SEQ   512
#define BATCH 1024
#define TAGS  32
#define START_TAG 30
#define END_TAG   31
#define WARPS_PER_BLOCK 4
#define THREADS_PER_BLOCK (WARPS_PER_BLOCK * 32)
#define NBLOCKS (BATCH / (WARPS_PER_BLOCK * 2))   // 128

__global__ __launch_bounds__(THREADS_PER_BLOCK, 1)
void crf_fwd_kernel(const float* __restrict__ feats,
                    const float* __restrict__ mask,
                    const float* __restrict__ trans,
                    float* __restrict__ out)
{
    const int lane = threadIdx.x & 31;
    const int warp = threadIdx.x >> 5;
    const int gw   = blockIdx.x * WARPS_PER_BLOCK + warp;
    const int half = lane >> 4;          // which batch within the warp
    const int s    = lane & 15;          // sub-lane within the 16-lane segment
    const int b    = gw * 2 + half;      // global batch index
    const int j0   = 2 * s;
    const int j1   = 2 * s + 1;

    // ---- E = exp(T), rows j0/j1 in registers -----------------------------
    float e0[TAGS], e1[TAGS];
#pragma unroll
    for (int i = 0; i < TAGS; ++i) {
        e0[i] = __expf(trans[j0 * TAGS + i]);
        e1[i] = __expf(trans[j1 * TAGS + i]);
    }
    const float eEnd0 = __expf(trans[END_TAG * TAGS + j0]);
    const float eEnd1 = __expf(trans[END_TAG * TAGS + j1]);

    // ---- init: alpha0 = NEG everywhere except START=0  ->  p = e_START ---
    float p0 = (j0 == START_TAG) ? 1.0f : 0.0f;
    float p1 = (j1 == START_TAG) ? 1.0f : 0.0f;
    float M  = 0.0f;

    // ---- feats as float2, software-pipelined 8 steps ahead ---------------
    const float2* __restrict__ F2 = reinterpret_cast<const float2*>(feats);
    const int fstride = BATCH * TAGS / 2;        // 16384 float2 per timestep
    const int fbase   = b * (TAGS / 2) + s;

    float2 fb[8];
    float  mb[8];
#pragma unroll
    for (int u = 0; u < 8; ++u) {
        fb[u] = F2[u * fstride + fbase];
        mb[u] = mask[u * BATCH + b];
    }

    for (int blk = 0; blk < SEQ / 8; ++blk) {
        const int t0 = blk * 8;

#pragma unroll
        for (int u = 0; u < 8; ++u) {
            const float2 f = fb[u];
            const float  m = mb[u];

            // prefetch t+8 (wraps harmlessly on the last block)
            const int tp = (t0 + 8 + u) & (SEQ - 1);
            fb[u] = F2[tp * fstride + fbase];
            mb[u] = mask[tp * BATCH + b];

            const float ef0 = __expf(f.x);
            const float ef1 = __expf(f.y);

            // q = E * p : broadcast p pairs from each sub-lane, 4 accums/tag
            float c00 = 0.f, c01 = 0.f, c02 = 0.f, c03 = 0.f;
            float c10 = 0.f, c11 = 0.f, c12 = 0.f, c13 = 0.f;
#pragma unroll
            for (int k = 0; k < 16; ++k) {
                const float v0 = __shfl_sync(0xffffffffu, p0, k, 16); // p[2k]
                const float v1 = __shfl_sync(0xffffffffu, p1, k, 16); // p[2k+1]
                if (k & 1) {
                    c01 = fmaf(e0[2 * k],     v0, c01);
                    c03 = fmaf(e0[2 * k + 1], v1, c03);
                    c11 = fmaf(e1[2 * k],     v0, c11);
                    c13 = fmaf(e1[2 * k + 1], v1, c13);
                } else {
                    c00 = fmaf(e0[2 * k],     v0, c00);
                    c02 = fmaf(e0[2 * k + 1], v1, c02);
                    c10 = fmaf(e1[2 * k],     v0, c10);
                    c12 = fmaf(e1[2 * k + 1], v1, c12);
                }
            }
            const float q0 = (c00 + c01) + (c02 + c03);
            const float q1 = (c10 + c11) + (c12 + c13);

            const float r0 = q0 * ef0;
            const float r1 = q1 * ef1;

            // mask select (mask is 0/1; alpha-blend degenerates to select)
            const bool upd = (m != 0.0f);
            p0 = upd ? r0 : p0;
            p1 = upd ? r1 : p1;
        }

        // ---- renormalize every 8 steps: s = max(p), p /= s, M += log s ---
        float w = fmaxf(p0, p1);
#pragma unroll
        for (int off = 1; off < 16; off <<= 1)
            w = fmaxf(w, __shfl_xor_sync(0xffffffffu, w, off, 16));
        const float inv = 1.0f / w;
        p0 *= inv;
        p1 *= inv;
        M += __logf(w);
    }

    // ---- epilogue: out[b] = M + log( sum_j p[j] * exp(T[END,j]) ) --------
    float wsum = p0 * eEnd0 + p1 * eEnd1;
#pragma unroll
    for (int off = 1; off < 16; off <<= 1)
        wsum += __shfl_xor_sync(0xffffffffu, wsum, off, 16);

    if (s == 0)
        out[b] = M + __logf(wsum);
}

extern "C" void kernel_launch(void* const* d_in, const int* in_sizes, int n_in,
                              void* d_out, int out_size)
{
    const float* feats = (const float*)d_in[0];   // (512,1024,32) f32
    const float* msk   = (const float*)d_in[1];   // (512,1024)    f32
    const float* trans = (const float*)d_in[2];   // (32,32)       f32
    float*       out   = (float*)d_out;           // (1024,)       f32

    crf_fwd_kernel<<<NBLOCKS, THREADS_PER_BLOCK>>>(feats, msk, trans, out);
}